// round 2
// baseline (speedup 1.0000x reference)
#include <cuda_runtime.h>
#include <cuda_bf16.h>
#include <cstdint>

// FirstSpikeDetector: out[b][t] = 1 iff spike_train[b][t] is the first nonzero
// in row b, else 0. Input values are exact 0.0f / 1.0f.
//
// R2 restructure:
//  - Issue the first-chunk load, then immediately stream zeros to the 480
//    float4 vectors (elements 128..2047) that can never depend on the scan
//    (the first spike is in the first 128 elems with P ~= 1 - 1.4e-6).
//    This hides the ~600-cycle DRAM load latency behind 15 independent
//    STG.128s per lane instead of serializing scan -> store.
//  - __stcs streaming stores: output is write-once never-read; evict-first
//    reduces dirty-L2 accumulation backpressure (output size ~= L2 size).
//  - Rare path (no spike in first 128): scan remaining chunks, __syncwarp()
//    fence, then a single scalar 1.0f overwrite of the already-zeroed slot.

static constexpr int T  = 2048;   // time steps per row
static constexpr int TV = T / 4;  // float4s per row (512)

__global__ void __launch_bounds__(256)
first_spike_kernel(const float* __restrict__ in, float* __restrict__ out, int rows)
{
    const int gtid = blockIdx.x * blockDim.x + threadIdx.x;
    const int warp = gtid >> 5;
    const int lane = gtid & 31;
    if (warp >= rows) return;

    const float4* __restrict__ row_in  = reinterpret_cast<const float4*>(in)  + (size_t)warp * TV;
    float4* __restrict__       row_out = reinterpret_cast<float4*>(out)       + (size_t)warp * TV;

    // Issue the scan load for the first 128 elements (vectors 0..31).
    float4 v = __ldcs(&row_in[lane]);

    const float4 z = make_float4(0.0f, 0.0f, 0.0f, 0.0f);

    // Independent zero stream for vectors 32..511 while the load is in flight.
    #pragma unroll
    for (int i = 32 + lane; i < TV; i += 32) {
        __stcs(&row_out[i], z);
    }

    // Resolve the scan of the first chunk.
    const bool any = (v.x != 0.0f) | (v.y != 0.0f) | (v.z != 0.0f) | (v.w != 0.0f);
    const unsigned m = __ballot_sync(0xffffffffu, any);

    if (m != 0u) {
        // Common path: first spike lives in vectors 0..31.
        const int src = __ffs(m) - 1;
        float4 w = z;
        if (lane == src) {
            int sub;
            if      (v.x != 0.0f) sub = 0;
            else if (v.y != 0.0f) sub = 1;
            else if (v.z != 0.0f) sub = 2;
            else                  sub = 3;
            (&w.x)[sub] = 1.0f;
        }
        __stcs(&row_out[lane], w);
    } else {
        // Rare path (P ~ 1.4e-6 per row): zero vectors 0..31, then keep scanning.
        __stcs(&row_out[lane], z);

        int first = -1;
        #pragma unroll 1
        for (int base = 128; base < T; base += 128) {
            float4 u = row_in[(base >> 2) + lane];
            bool a2 = (u.x != 0.0f) | (u.y != 0.0f) | (u.z != 0.0f) | (u.w != 0.0f);
            unsigned m2 = __ballot_sync(0xffffffffu, a2);
            if (m2) {
                int s2 = __ffs(m2) - 1;
                if (lane == s2) {
                    int sub;
                    if      (u.x != 0.0f) sub = 0;
                    else if (u.y != 0.0f) sub = 1;
                    else if (u.z != 0.0f) sub = 2;
                    else                  sub = 3;
                    first = base + (s2 << 2) + sub;
                }
                break;   // m2 is warp-uniform; all lanes exit together
            }
        }

        // Order the zero stores (from any lane) before the scalar overwrite.
        __syncwarp();
        if (first >= 0) {
            reinterpret_cast<float*>(row_out)[first] = 1.0f;
        }
    }
}

extern "C" void kernel_launch(void* const* d_in, const int* in_sizes, int n_in,
                              void* d_out, int out_size)
{
    const float* in = (const float*)d_in[0];
    float* out = (float*)d_out;

    const int rows = in_sizes[0] / T;                      // 16384
    const int threads = 256;                               // 8 warps/block
    const int blocks = (rows * 32 + threads - 1) / threads; // 2048

    first_spike_kernel<<<blocks, threads>>>(in, out, rows);
}